// round 13
// baseline (speedup 1.0000x reference)
#include <cuda_runtime.h>
#include <cuda_fp16.h>
#include <stdint.h>

#define BB 64
#define TE 1024
#define TO 1000
#define AD 256
#define ED 256
#define HD 256
#define NM 80
#define NCTA 296

// ---------------- static device scratch ----------------
__device__ __half g_attn_t[(size_t)BB*AD*TE];   // 32 MB : fp16 enc projection, TRANSPOSED [b][a][t]
__device__ __half g_enc_h [(size_t)BB*TE*ED];   // 32 MB : fp16 enc_outputs [b][t][d]
__device__ float  g_pre2  [(size_t)TO*BB*HD];   // prenet(all steps) [t*64+b][k]
__device__ float  g_gpre  [(size_t)TO*4*HD*BB]; // gate partial (pre+biases) [t][r][b]
__device__ float  g_q     [BB*AD];
__device__ float  g_h     [2][BB*HD];
__device__ float  g_ctxp  [512*ED];             // per (b, eighth) ctx partials
__device__ float  g_sump  [512];
__device__ float  g_hhist [(size_t)TO*BB*HD];   // h history (for deferred heads)
__device__ float  g_chist [(size_t)TO*BB*ED];   // ctx history
__device__ int    g_len   [BB];
__device__ unsigned g_arrive;
__device__ unsigned g_ticketA;

__device__ __forceinline__ float tanh_acc(float x){
    x = fminf(fmaxf(x, -15.f), 15.f);
    float e = __expf(2.f*x);
    return __fdividef(e - 1.f, e + 1.f);
}
__device__ __forceinline__ float sigm(float x){
    return __fdividef(1.f, 1.f + __expf(-x));
}

// ---------------- prologue 1: enc projection (fp16, transposed) + enc fp16 copy ----
__global__ void __launch_bounds__(256) k_prep_enc(const float* __restrict__ enc,
                                                  const float* __restrict__ Wenc,
                                                  const float* __restrict__ benc){
    __shared__ float4 enc_s[16][64];
    int tid = threadIdx.x;
    int b  = blockIdx.y;
    int t0 = blockIdx.x * 16;
    int base = (b*TE + t0)*ED;
    const float4* ev = (const float4*)(enc + base);
    for (int idx = tid; idx < 16*64; idx += 256) enc_s[idx>>6][idx&63] = ev[idx];
    for (int idx = tid; idx < 16*ED; idx += 256) g_enc_h[base+idx] = __float2half(enc[base+idx]);
    __syncthreads();
    float acc[16];
    #pragma unroll
    for (int i=0;i<16;i++) acc[i]=0.f;
    const float4* wv = (const float4*)Wenc + tid*64;
    for (int e=0;e<64;e++){
        float4 w = wv[e];
        #pragma unroll
        for (int i=0;i<16;i++){
            float4 x = enc_s[i][e];
            acc[i] += w.x*x.x + w.y*x.y + w.z*x.z + w.w*x.w;
        }
    }
    float bv = benc[tid];
    #pragma unroll
    for (int i=0;i<16;i++)
        g_attn_t[((size_t)(b*AD + tid))*TE + t0 + i] = __float2half(acc[i] + bv);
}

// ---------------- prologue 2: prenet for all steps ----------------
#define TT 25
__global__ void __launch_bounds__(256) k_prenet(const float* __restrict__ tm,
                                                const float* __restrict__ W1, const float* __restrict__ b1,
                                                const float* __restrict__ W2, const float* __restrict__ b2){
    __shared__ float prev_s[TT][80];
    __shared__ float pre1_s[TT][256];
    int tid = threadIdx.x;
    int b  = blockIdx.y;
    int t0 = blockIdx.x * TT;
    for (int idx = tid; idx < TT*80; idx += 256){
        int tt = idx/80, m = idx%80;
        int t = t0 + tt;
        prev_s[tt][m] = (t==0) ? 0.f : tm[(b*TO + (t-1))*NM + m];
    }
    __syncthreads();
    float acc[TT];
    #pragma unroll
    for (int i=0;i<TT;i++) acc[i]=0.f;
    {
        const float4* w1v = (const float4*)W1 + tid*20;
        for (int m=0;m<20;m++){
            float4 w = w1v[m];
            #pragma unroll
            for (int i=0;i<TT;i++){
                float4 x = ((const float4*)prev_s[i])[m];
                acc[i] += w.x*x.x + w.y*x.y + w.z*x.z + w.w*x.w;
            }
        }
    }
    float bv1 = b1[tid];
    #pragma unroll
    for (int i=0;i<TT;i++) pre1_s[i][tid] = fmaxf(acc[i] + bv1, 0.f);
    __syncthreads();
    #pragma unroll
    for (int i=0;i<TT;i++) acc[i]=0.f;
    {
        const float4* w2v = (const float4*)W2 + tid*64;
        for (int m=0;m<64;m++){
            float4 w = w2v[m];
            #pragma unroll
            for (int i=0;i<TT;i++){
                float4 x = ((const float4*)pre1_s[i])[m];
                acc[i] += w.x*x.x + w.y*x.y + w.z*x.z + w.w*x.w;
            }
        }
    }
    float bv2 = b2[tid];
    #pragma unroll
    for (int i=0;i<TT;i++) g_pre2[(size_t)(t0+i)*(BB*HD) + b*HD + tid] = fmaxf(acc[i] + bv2, 0.f);
}

// ------- prologue 3: gpre = Wih[:, :256] @ pre2 + biases — 128x128x32 tiled GEMM -------
__global__ void __launch_bounds__(256) k_pregate(const float* __restrict__ Wih,
                                                 const float* __restrict__ bih,
                                                 const float* __restrict__ bhh){
    __shared__ float As[32][132];     // [k][m]
    __shared__ float Bs[32][132];     // [k][r]
    int tid = threadIdx.x;
    int r0 = blockIdx.x * 128;
    int m0 = blockIdx.y * 128;
    int tx = tid & 15, ty = tid >> 4;
    float acc[8][8];
    #pragma unroll
    for (int i=0;i<8;i++)
        #pragma unroll
        for (int j=0;j<8;j++) acc[i][j]=0.f;
    for (int k0 = 0; k0 < 256; k0 += 32){
        for (int i = tid; i < 128*8; i += 256){
            int m = i >> 3, k4 = i & 7;
            float4 v = *(const float4*)&g_pre2[(size_t)(m0+m)*HD + k0 + k4*4];
            As[k4*4+0][m]=v.x; As[k4*4+1][m]=v.y; As[k4*4+2][m]=v.z; As[k4*4+3][m]=v.w;
            float4 w = *(const float4*)&Wih[(size_t)(r0+m)*512 + k0 + k4*4];
            Bs[k4*4+0][m]=w.x; Bs[k4*4+1][m]=w.y; Bs[k4*4+2][m]=w.z; Bs[k4*4+3][m]=w.w;
        }
        __syncthreads();
        #pragma unroll
        for (int k=0;k<32;k++){
            float am[8], bn[8];
            #pragma unroll
            for (int i=0;i<8;i++) am[i] = As[k][ty*8+i];
            #pragma unroll
            for (int j=0;j<8;j++) bn[j] = Bs[k][tx*8+j];
            #pragma unroll
            for (int i=0;i<8;i++)
                #pragma unroll
                for (int j=0;j<8;j++) acc[i][j] = fmaf(am[i], bn[j], acc[i][j]);
        }
        __syncthreads();
    }
    #pragma unroll
    for (int i=0;i<8;i++){
        int m = m0 + ty*8 + i, t = m >> 6, b = m & 63;
        #pragma unroll
        for (int j=0;j<8;j++){
            int r = r0 + tx*8 + j;
            g_gpre[((size_t)t*1024 + r)*64 + b] = acc[i][j] + bih[r] + bhh[r];
        }
    }
}

// ---------------- prologue 4: init state, lengths, partial-zeroing, counters ----
__global__ void k_init(const float* __restrict__ bdec, const float* __restrict__ mask){
    __shared__ float red[256];
    int b = blockIdx.x, tid = threadIdx.x;
    g_h[0][b*HD+tid] = 0.f;
    g_q[b*AD+tid]    = bdec[tid];
    for (int i = b*256 + tid; i < 512*ED; i += 64*256) g_ctxp[i] = 0.f;
    if (tid < 8) g_sump[b*8 + tid] = 0.f;
    float s = 0.f;
    for (int i=tid;i<TE;i+=256) s += mask[b*TE+i];
    red[tid]=s; __syncthreads();
    for (int off=128; off; off>>=1){ if (tid<off) red[tid]+=red[tid+off]; __syncthreads(); }
    if (tid==0) g_len[b] = (int)(red[0] + 0.5f);
    if (b==0 && tid==0){ g_arrive = 0u; g_ticketA = 0u; }
}

// ---------------- fence-free grid barrier (release/acquire, no CCTL.IVALL) ------
__device__ __forceinline__ void gsync(unsigned &gen){
    __syncthreads();
    if (threadIdx.x == 0){
        gen += NCTA;
        unsigned* p = &g_arrive;
        asm volatile("red.release.gpu.add.u32 [%0], 1;" :: "l"(p) : "memory");
        unsigned v;
        do {
            asm volatile("ld.relaxed.gpu.u32 %0, [%1];" : "=r"(v) : "l"(p) : "memory");
        } while (v < gen);
        asm volatile("ld.acquire.gpu.u32 %0, [%1];" : "=r"(v) : "l"(p) : "memory");
    }
    __syncthreads();
}

// ---------------- persistent main kernel ----------------
struct SAx {
    __align__(16) char buf[2][16384];   // double-buffered 16KB tiles
    __half qhalf[AD];
    float  v[AD];
    float  ep[8][33];
    float  es[128];
    float  wctx[8][264];
};
struct SG { float x[8][516]; float rs[8]; float gsm[32][9]; };
struct SQ { float h[8][260]; };
union  SU { SAx a; SG g; SQ q; };

__global__ void __launch_bounds__(256,2) k_main(
        const float* __restrict__ vw,  const float* __restrict__ vb,
        const float* __restrict__ Wih, const float* __restrict__ Whh,
        const float* __restrict__ Wdec, const float* __restrict__ bdec){
    __shared__ SU sm;
    __shared__ unsigned s_chunk;
    const int c   = blockIdx.x;
    const int tid = threadIdx.x;
    const int l   = tid & 31, w = tid >> 5;
    unsigned gen = 0;
    const float vb0 = vb[0];
    float c_state = 0.f;                      // cell state (valid in G-CTAs, tid<64)
    const unsigned bufbase = (unsigned)__cvta_generic_to_shared(&sm.a.buf[0][0]);

    for (int t = 0; t < TO; t++){
        // ======== Phase A : cp.async-staged attention — dynamic chunks ========
        const unsigned baseA = (unsigned)t * 1024u;
        for (;;){
            if (tid == 0) s_chunk = atomicAdd(&g_ticketA, 1u);
            __syncthreads();                               // publish s_chunk
            const unsigned rel = s_chunk - baseA;          // uniform snapshot
            const bool done = (rel >= 512u);
            if (!done){
                const int b  = (int)(rel >> 3), e8 = (int)(rel & 7);
                const int t0 = e8 * 128;
                const int len = g_len[b];
                if (t0 < len){
                    // -- initial prefetch: energy tiles 0,1 ([256a][32t], 64B per a-row) --
                    #pragma unroll
                    for (int kk = 0; kk < 2; kk++){
                        unsigned dst = bufbase + (kk << 14) + (tid << 6);
                        const char* src = (const char*)(g_attn_t + ((size_t)(b*AD + tid))*TE + t0 + (kk<<5));
                        #pragma unroll
                        for (int s2=0;s2<4;s2++)
                            asm volatile("cp.async.cg.shared.global [%0], [%1], 16;"
                                         :: "r"(dst + s2*16), "l"(src + s2*16));
                        asm volatile("cp.async.commit_group;" ::: "memory");
                    }
                    // -- stage q (fp16) + v (f32) --
                    sm.a.qhalf[tid] = __float2half(__ldcg(&g_q[b*AD + tid]));
                    sm.a.v[tid]     = vw[tid];
                    float ca[8];
                    #pragma unroll
                    for (int i=0;i<8;i++) ca[i] = 0.f;

                    #pragma unroll 1
                    for (int k = 0; k < 8; k++){
                        if (k < 7) asm volatile("cp.async.wait_group 1;" ::: "memory");
                        else       asm volatile("cp.async.wait_group 0;" ::: "memory");
                        __syncthreads();
                        if (k < 4){
                            // ---- energy tile k from buf[k&1]: warp w owns a=w*32..+32, lane l owns t ----
                            const __half* bt = (const __half*)sm.a.buf[k & 1];
                            const __half2* qp = (const __half2*)sm.a.qhalf;
                            float e1 = 0.f, e2 = 0.f;
                            #pragma unroll
                            for (int ai = 0; ai < 16; ai++){
                                const int a = (w << 5) + (ai << 1);
                                __half2 hx = __halves2half2(bt[a*32 + l], bt[(a+1)*32 + l]);
                                hx = __hadd2(hx, qp[a >> 1]);
                                unsigned r0;
                                asm("tanh.approx.f16x2 %0, %1;" : "=r"(r0) : "r"(*(unsigned*)&hx));
                                float2 tf = __half22float2(*(__half2*)&r0);
                                e1 = fmaf(sm.a.v[a],   tf.x, e1);
                                e2 = fmaf(sm.a.v[a+1], tf.y, e2);
                            }
                            sm.a.ep[w][l] = e1 + e2;
                            __syncthreads();      // ep ready; buffer free for reuse
                            // prefetch tile k+2 (energy if k<2, else context tile k-2)
                            if (k < 2){
                                const int kk = k + 2;
                                unsigned dst = bufbase + ((kk & 1) << 14) + (tid << 6);
                                const char* src = (const char*)(g_attn_t + ((size_t)(b*AD + tid))*TE + t0 + (kk<<5));
                                #pragma unroll
                                for (int s2=0;s2<4;s2++)
                                    asm volatile("cp.async.cg.shared.global [%0], [%1], 16;"
                                                 :: "r"(dst + s2*16), "l"(src + s2*16));
                            } else {
                                const int jj = k - 2;     // context tile, buffer jj&1 == (k+2)&1
                                const int trow = tid >> 3, seg = tid & 7;
                                unsigned dst = bufbase + ((jj & 1) << 14) + trow*512 + (seg << 4);
                                const char* src = (const char*)(g_enc_h + ((size_t)(b*TE + t0 + (jj<<5) + trow))*ED) + (seg << 4);
                                #pragma unroll
                                for (int s2=0;s2<4;s2++)
                                    asm volatile("cp.async.cg.shared.global [%0], [%1], 16;"
                                                 :: "r"(dst + s2*128), "l"(src + s2*128));
                            }
                            asm volatile("cp.async.commit_group;" ::: "memory");
                            if (tid < 32){
                                float s = 0.f;
                                #pragma unroll
                                for (int ww=0; ww<8; ww++) s += sm.a.ep[ww][tid];
                                sm.a.es[(k<<5) + tid] = (t0 + (k<<5) + tid < len) ? __expf(s + vb0) : 0.f;
                            }
                        } else {
                            // ---- context tile j=k-4 from buf[k&1]: warp w owns 4 t-rows, lane l owns d=8l..+8 ----
                            const int j = k - 4;
                            const uint4* bt4 = (const uint4*)sm.a.buf[k & 1];
                            #pragma unroll
                            for (int i=0;i<4;i++){
                                const int trow = (w << 2) + i;
                                float ev = sm.a.es[(j<<5) + trow];
                                uint4 x = bt4[trow*32 + l];
                                float2 f0 = __half22float2(*(__half2*)&x.x);
                                float2 f1 = __half22float2(*(__half2*)&x.y);
                                float2 f2 = __half22float2(*(__half2*)&x.z);
                                float2 f3 = __half22float2(*(__half2*)&x.w);
                                ca[0] = fmaf(ev, f0.x, ca[0]); ca[1] = fmaf(ev, f0.y, ca[1]);
                                ca[2] = fmaf(ev, f1.x, ca[2]); ca[3] = fmaf(ev, f1.y, ca[3]);
                                ca[4] = fmaf(ev, f2.x, ca[4]); ca[5] = fmaf(ev, f2.y, ca[5]);
                                ca[6] = fmaf(ev, f3.x, ca[6]); ca[7] = fmaf(ev, f3.y, ca[7]);
                            }
                            __syncthreads();      // reads done; buffer free
                            if (k < 6){
                                const int jj = k - 2;
                                const int trow = tid >> 3, seg = tid & 7;
                                unsigned dst = bufbase + ((jj & 1) << 14) + trow*512 + (seg << 4);
                                const char* src = (const char*)(g_enc_h + ((size_t)(b*TE + t0 + (jj<<5) + trow))*ED) + (seg << 4);
                                #pragma unroll
                                for (int s2=0;s2<4;s2++)
                                    asm volatile("cp.async.cg.shared.global [%0], [%1], 16;"
                                                 :: "r"(dst + s2*128), "l"(src + s2*128));
                                asm volatile("cp.async.commit_group;" ::: "memory");
                            }
                        }
                    }
                    // ---- chunk epilogue: combine wctx, write partials ----
                    #pragma unroll
                    for (int j2=0;j2<8;j2++) sm.a.wctx[w][(l<<3)+j2] = ca[j2];
                    __syncthreads();
                    {
                        float s = 0.f;
                        #pragma unroll
                        for (int ww=0;ww<8;ww++) s += sm.a.wctx[ww][tid];
                        __stcg(&g_ctxp[(size_t)(b*8 + e8)*ED + tid], s);
                    }
                    if (tid < 32){
                        float s = sm.a.es[tid] + sm.a.es[tid+32] + sm.a.es[tid+64] + sm.a.es[tid+96];
                        #pragma unroll
                        for (int off=16; off; off>>=1) s += __shfl_xor_sync(0xffffffffu, s, off);
                        if (tid == 0) __stcg(&g_sump[b*8 + e8], s);
                    }
                }
            }
            __syncthreads();                 // protect s_chunk + smem reuse on ALL paths
            if (done) break;
        }
        gsync(gen);
        if (c == 0 && tid == 0) atomicMax(&g_ticketA, (unsigned)(t+1) * 1024u);

        // ======== Phase G : gates + cell update (CTAs 0..255 : jblock x bblock) ========
        if (c < 256){
            const int jb = c >> 3;              // 32 j-blocks of 8
            const int b0 = (c & 7) * 8;         // 8 b-blocks of 8
            if (tid < 8){
                int b = b0 + tid;
                float ssum = 0.f;
                #pragma unroll
                for (int e=0;e<8;e++) ssum += __ldcg(&g_sump[b*8 + e]);
                sm.g.rs[tid] = __fdividef(1.f, ssum);
            }
            __syncthreads();
            const int ph = t & 1;
            for (int idx = tid; idx < 8*512; idx += 256){
                int bb = idx >> 9, k = idx & 511;
                int b = b0 + bb;
                float v;
                if (k < 256){
                    float s = 0.f;
                    #pragma unroll
                    for (int e=0;e<8;e++) s += __ldcg(&g_ctxp[(size_t)(b*8+e)*ED + k]);
                    v = s * sm.g.rs[bb];
                } else {
                    v = __ldcg(&g_h[ph][b*HD + (k - 256)]);
                }
                sm.g.x[bb][k] = v;
            }
            __syncthreads();
            // ctx history store (only j-block 0 CTAs own it)
            if (jb == 0){
                for (int idx = tid; idx < 8*256; idx += 256){
                    int bb = idx >> 8, k = idx & 255;
                    __stcg(&g_chist[(size_t)t*(BB*ED) + (b0+bb)*ED + k], sm.g.x[bb][k]);
                }
            }
            // GEMM: thread = (row rr = 4gates x 8j, bb)
            const int rr = tid >> 3, bb = tid & 7;
            const int r = (rr >> 3)*256 + jb*8 + (rr & 7);
            const int b = b0 + bb;
            float a0 = __ldcg(&g_gpre[((size_t)t*1024 + r)*64 + b]);
            float a1 = 0.f, a2 = 0.f, a3 = 0.f;
            const float4* w1 = (const float4*)Wih + (size_t)r*128 + 64;   // ctx cols
            const float4* w2 = (const float4*)Whh + (size_t)r*64;
            const float4* x1 = (const float4*)sm.g.x[bb];
            const float4* x2 = x1 + 64;
            #pragma unroll 4
            for (int k=0;k<64;k++){
                float4 ww = w1[k], xx = x1[k];
                a0 = fmaf(ww.x,xx.x,a0); a1 = fmaf(ww.y,xx.y,a1);
                a2 = fmaf(ww.z,xx.z,a2); a3 = fmaf(ww.w,xx.w,a3);
            }
            #pragma unroll 4
            for (int k=0;k<64;k++){
                float4 ww = w2[k], xx = x2[k];
                a0 = fmaf(ww.x,xx.x,a0); a1 = fmaf(ww.y,xx.y,a1);
                a2 = fmaf(ww.z,xx.z,a2); a3 = fmaf(ww.w,xx.w,a3);
            }
            sm.g.gsm[rr][bb] = (a0+a1) + (a2+a3);
            __syncthreads();
            if (tid < 64){
                const int jj = tid >> 3, bb2 = tid & 7;
                float gi = sm.g.gsm[ 0 + jj][bb2];
                float gf = sm.g.gsm[ 8 + jj][bb2];
                float gg = sm.g.gsm[16 + jj][bb2];
                float go = sm.g.gsm[24 + jj][bb2];
                float cn = sigm(gf)*c_state + sigm(gi)*tanh_acc(gg);
                float hn = sigm(go)*tanh_acc(cn);
                c_state = cn;
                const int b2 = b0 + bb2, j = jb*8 + jj;
                __stcg(&g_h[(t+1)&1][b2*HD + j], hn);
                __stcg(&g_hhist[(size_t)t*(BB*HD) + b2*HD + j], hn);
            }
        }
        gsync(gen);

        // ======== Phase Q : next query q = Wdec @ h_new + bdec (CTAs 0..255) ========
        if (c < 256){
            const int ra = c >> 3, b0 = (c & 7) * 8;
            const int ph1 = (t+1) & 1;
            for (int idx = tid; idx < 8*256; idx += 256)
                sm.q.h[idx >> 8][idx & 255] = __ldcg(&g_h[ph1][(b0 + (idx >> 8))*HD + (idx & 255)]);
            __syncthreads();
            if (tid < 64){
                const int ar = tid >> 3, bb = tid & 7;
                const int a = ra*8 + ar;
                float q0 = bdec[a], q1 = 0.f, q2 = 0.f, q3 = 0.f;
                const float4* wv = (const float4*)Wdec + (size_t)a*64;
                const float4* hv = (const float4*)sm.q.h[bb];
                #pragma unroll 8
                for (int k=0;k<64;k++){
                    float4 ww = wv[k], xx = hv[k];
                    q0 = fmaf(ww.x,xx.x,q0); q1 = fmaf(ww.y,xx.y,q1);
                    q2 = fmaf(ww.z,xx.z,q2); q3 = fmaf(ww.w,xx.w,q3);
                }
                __stcg(&g_q[(b0+bb)*AD + a], (q0+q1) + (q2+q3));
            }
            __syncthreads();
        }
        gsync(gen);
    }
}

// ---------------- epilogue: mel + stop heads from history ----------------
__global__ void __launch_bounds__(256) k_heads(const float* __restrict__ melW,
                                               const float* __restrict__ melb,
                                               const float* __restrict__ stopW,
                                               const float* __restrict__ stopb,
                                               float* __restrict__ out){
    __shared__ float comb[16][520];
    const int b = blockIdx.y, t0 = blockIdx.x * 16;
    const int tid = threadIdx.x;
    for (int idx = tid; idx < 16*256; idx += 256){
        int tt = idx >> 8, k = idx & 255;
        int t = t0 + tt;
        float hv = 0.f, cv = 0.f;
        if (t < TO){
            hv = g_hhist[(size_t)t*(BB*HD) + b*HD + k];
            cv = g_chist[(size_t)t*(BB*ED) + b*ED + k];
        }
        comb[tt][k] = hv; comb[tt][256+k] = cv;
    }
    __syncthreads();
    for (int idx = tid; idx < 16*81; idx += 256){
        int tt = idx / 81, n = idx - tt*81;
        int t = t0 + tt;
        if (t >= TO) continue;
        const float4* wv = (const float4*)((n < 80) ? (melW + n*512) : stopW);
        float a0 = (n < 80) ? melb[n] : stopb[0];
        float a1 = 0.f, a2 = 0.f, a3 = 0.f;
        const float4* cv = (const float4*)comb[tt];
        #pragma unroll 4
        for (int k=0;k<128;k++){
            float4 ww = wv[k], xx = cv[k];
            a0 = fmaf(ww.x,xx.x,a0); a1 = fmaf(ww.y,xx.y,a1);
            a2 = fmaf(ww.z,xx.z,a2); a3 = fmaf(ww.w,xx.w,a3);
        }
        float r = (a0+a1) + (a2+a3);
        if (n < 80) out[(b*TO + t)*NM + n] = r;
        else        out[(size_t)BB*TO*NM + b*TO + t] = r;
    }
}

// ---------------- launch ----------------
extern "C" void kernel_launch(void* const* d_in, const int* in_sizes, int n_in,
                              void* d_out, int out_size){
    (void)in_sizes; (void)n_in; (void)out_size;
    const float* enc  = (const float*)d_in[0];
    const float* tm   = (const float*)d_in[1];
    const float* Wenc = (const float*)d_in[2];
    const float* benc = (const float*)d_in[3];
    const float* Wdec = (const float*)d_in[4];
    const float* bdec = (const float*)d_in[5];
    const float* vw   = (const float*)d_in[6];
    const float* vb   = (const float*)d_in[7];
    const float* W1   = (const float*)d_in[8];
    const float* b1   = (const float*)d_in[9];
    const float* W2   = (const float*)d_in[10];
    const float* b2   = (const float*)d_in[11];
    const float* Wih  = (const float*)d_in[12];
    const float* Whh  = (const float*)d_in[13];
    const float* bih  = (const float*)d_in[14];
    const float* bhh  = (const float*)d_in[15];
    const float* melW = (const float*)d_in[16];
    const float* melb = (const float*)d_in[17];
    const float* stopW= (const float*)d_in[18];
    const float* stopb= (const float*)d_in[19];
    const float* mask = (const float*)d_in[20];
    float* out = (float*)d_out;

    k_prep_enc<<<dim3(64,64),256>>>(enc, Wenc, benc);
    k_prenet  <<<dim3(40,64),256>>>(tm, W1, b1, W2, b2);
    k_pregate <<<dim3(8,500),256>>>(Wih, bih, bhh);
    k_init    <<<64,256>>>(bdec, mask);
    k_main    <<<NCTA,256>>>(vw, vb, Wih, Whh, Wdec, bdec);
    k_heads   <<<dim3(63,64),256>>>(melW, melb, stopW, stopb, out);
}

// round 14
// speedup vs baseline: 1.2422x; 1.2422x over previous
#include <cuda_runtime.h>
#include <cuda_fp16.h>

#define BB 64
#define TE 1024
#define TO 1000
#define AD 256
#define ED 256
#define HD 256
#define NM 80
#define NCTA 296

// ---------------- static device scratch ----------------
__device__ __half g_attn_t[(size_t)BB*AD*TE];   // 32 MB : fp16 enc projection, TRANSPOSED [b][a][t]
__device__ __half g_enc_h [(size_t)BB*TE*ED];   // 32 MB : fp16 enc_outputs [b][t][d]
__device__ float  g_pre2  [(size_t)TO*BB*HD];   // prenet(all steps) [t*64+b][k]
__device__ float  g_gpre  [(size_t)TO*4*HD*BB]; // gate partial (pre+biases) [t][r][b]
__device__ float  g_q     [BB*AD];
__device__ float  g_h     [2][BB*HD];
__device__ float  g_ctxp  [512*ED];             // per (b, eighth) ctx partials
__device__ float  g_sump  [512];
__device__ float  g_hhist [(size_t)TO*BB*HD];   // h history (for deferred heads)
__device__ float  g_chist [(size_t)TO*BB*ED];   // ctx history
__device__ int    g_len   [BB];
__device__ unsigned g_arrive;
__device__ unsigned g_ticketA;

__device__ __forceinline__ float tanh_acc(float x){
    x = fminf(fmaxf(x, -15.f), 15.f);
    float e = __expf(2.f*x);
    return __fdividef(e - 1.f, e + 1.f);
}
__device__ __forceinline__ float sigm(float x){
    return __fdividef(1.f, 1.f + __expf(-x));
}

// ---------------- prologue 1: enc projection (fp16, transposed) + enc fp16 copy ----
__global__ void __launch_bounds__(256) k_prep_enc(const float* __restrict__ enc,
                                                  const float* __restrict__ Wenc,
                                                  const float* __restrict__ benc){
    __shared__ float4 enc_s[16][64];
    int tid = threadIdx.x;
    int b  = blockIdx.y;
    int t0 = blockIdx.x * 16;
    int base = (b*TE + t0)*ED;
    const float4* ev = (const float4*)(enc + base);
    for (int idx = tid; idx < 16*64; idx += 256) enc_s[idx>>6][idx&63] = ev[idx];
    for (int idx = tid; idx < 16*ED; idx += 256) g_enc_h[base+idx] = __float2half(enc[base+idx]);
    __syncthreads();
    float acc[16];
    #pragma unroll
    for (int i=0;i<16;i++) acc[i]=0.f;
    const float4* wv = (const float4*)Wenc + tid*64;
    for (int e=0;e<64;e++){
        float4 w = wv[e];
        #pragma unroll
        for (int i=0;i<16;i++){
            float4 x = enc_s[i][e];
            acc[i] += w.x*x.x + w.y*x.y + w.z*x.z + w.w*x.w;
        }
    }
    float bv = benc[tid];
    #pragma unroll
    for (int i=0;i<16;i++)
        g_attn_t[((size_t)(b*AD + tid))*TE + t0 + i] = __float2half(acc[i] + bv);
}

// ---------------- prologue 2: prenet for all steps ----------------
#define TT 25
__global__ void __launch_bounds__(256) k_prenet(const float* __restrict__ tm,
                                                const float* __restrict__ W1, const float* __restrict__ b1,
                                                const float* __restrict__ W2, const float* __restrict__ b2){
    __shared__ float prev_s[TT][80];
    __shared__ float pre1_s[TT][256];
    int tid = threadIdx.x;
    int b  = blockIdx.y;
    int t0 = blockIdx.x * TT;
    for (int idx = tid; idx < TT*80; idx += 256){
        int tt = idx/80, m = idx%80;
        int t = t0 + tt;
        prev_s[tt][m] = (t==0) ? 0.f : tm[(b*TO + (t-1))*NM + m];
    }
    __syncthreads();
    float acc[TT];
    #pragma unroll
    for (int i=0;i<TT;i++) acc[i]=0.f;
    {
        const float4* w1v = (const float4*)W1 + tid*20;
        for (int m=0;m<20;m++){
            float4 w = w1v[m];
            #pragma unroll
            for (int i=0;i<TT;i++){
                float4 x = ((const float4*)prev_s[i])[m];
                acc[i] += w.x*x.x + w.y*x.y + w.z*x.z + w.w*x.w;
            }
        }
    }
    float bv1 = b1[tid];
    #pragma unroll
    for (int i=0;i<TT;i++) pre1_s[i][tid] = fmaxf(acc[i] + bv1, 0.f);
    __syncthreads();
    #pragma unroll
    for (int i=0;i<TT;i++) acc[i]=0.f;
    {
        const float4* w2v = (const float4*)W2 + tid*64;
        for (int m=0;m<64;m++){
            float4 w = w2v[m];
            #pragma unroll
            for (int i=0;i<TT;i++){
                float4 x = ((const float4*)pre1_s[i])[m];
                acc[i] += w.x*x.x + w.y*x.y + w.z*x.z + w.w*x.w;
            }
        }
    }
    float bv2 = b2[tid];
    #pragma unroll
    for (int i=0;i<TT;i++) g_pre2[(size_t)(t0+i)*(BB*HD) + b*HD + tid] = fmaxf(acc[i] + bv2, 0.f);
}

// ------- prologue 3: gpre = Wih[:, :256] @ pre2 + biases — 128x128x32 tiled GEMM -------
__global__ void __launch_bounds__(256) k_pregate(const float* __restrict__ Wih,
                                                 const float* __restrict__ bih,
                                                 const float* __restrict__ bhh){
    __shared__ float As[32][132];     // [k][m]
    __shared__ float Bs[32][132];     // [k][r]
    int tid = threadIdx.x;
    int r0 = blockIdx.x * 128;
    int m0 = blockIdx.y * 128;
    int tx = tid & 15, ty = tid >> 4;
    float acc[8][8];
    #pragma unroll
    for (int i=0;i<8;i++)
        #pragma unroll
        for (int j=0;j<8;j++) acc[i][j]=0.f;
    for (int k0 = 0; k0 < 256; k0 += 32){
        for (int i = tid; i < 128*8; i += 256){
            int m = i >> 3, k4 = i & 7;
            float4 v = *(const float4*)&g_pre2[(size_t)(m0+m)*HD + k0 + k4*4];
            As[k4*4+0][m]=v.x; As[k4*4+1][m]=v.y; As[k4*4+2][m]=v.z; As[k4*4+3][m]=v.w;
            float4 w = *(const float4*)&Wih[(size_t)(r0+m)*512 + k0 + k4*4];
            Bs[k4*4+0][m]=w.x; Bs[k4*4+1][m]=w.y; Bs[k4*4+2][m]=w.z; Bs[k4*4+3][m]=w.w;
        }
        __syncthreads();
        #pragma unroll
        for (int k=0;k<32;k++){
            float am[8], bn[8];
            #pragma unroll
            for (int i=0;i<8;i++) am[i] = As[k][ty*8+i];
            #pragma unroll
            for (int j=0;j<8;j++) bn[j] = Bs[k][tx*8+j];
            #pragma unroll
            for (int i=0;i<8;i++)
                #pragma unroll
                for (int j=0;j<8;j++) acc[i][j] = fmaf(am[i], bn[j], acc[i][j]);
        }
        __syncthreads();
    }
    #pragma unroll
    for (int i=0;i<8;i++){
        int m = m0 + ty*8 + i, t = m >> 6, b = m & 63;
        #pragma unroll
        for (int j=0;j<8;j++){
            int r = r0 + tx*8 + j;
            g_gpre[((size_t)t*1024 + r)*64 + b] = acc[i][j] + bih[r] + bhh[r];
        }
    }
}

// ---------------- prologue 4: init state, lengths, partial-zeroing, counters ----
__global__ void k_init(const float* __restrict__ bdec, const float* __restrict__ mask){
    __shared__ float red[256];
    int b = blockIdx.x, tid = threadIdx.x;
    g_h[0][b*HD+tid] = 0.f;
    g_q[b*AD+tid]    = bdec[tid];
    for (int i = b*256 + tid; i < 512*ED; i += 64*256) g_ctxp[i] = 0.f;
    if (tid < 8) g_sump[b*8 + tid] = 0.f;
    float s = 0.f;
    for (int i=tid;i<TE;i+=256) s += mask[b*TE+i];
    red[tid]=s; __syncthreads();
    for (int off=128; off; off>>=1){ if (tid<off) red[tid]+=red[tid+off]; __syncthreads(); }
    if (tid==0) g_len[b] = (int)(red[0] + 0.5f);
    if (b==0 && tid==0){ g_arrive = 0u; g_ticketA = 0u; }
}

// ---------------- fence-free grid barrier (release/acquire, no CCTL.IVALL) ------
__device__ __forceinline__ void gsync(unsigned &gen){
    __syncthreads();
    if (threadIdx.x == 0){
        gen += NCTA;
        unsigned* p = &g_arrive;
        asm volatile("red.release.gpu.add.u32 [%0], 1;" :: "l"(p) : "memory");
        unsigned v;
        do {
            asm volatile("ld.relaxed.gpu.u32 %0, [%1];" : "=r"(v) : "l"(p) : "memory");
        } while (v < gen);
        asm volatile("ld.acquire.gpu.u32 %0, [%1];" : "=r"(v) : "l"(p) : "memory");
    }
    __syncthreads();
}

// ---------------- persistent main kernel ----------------
struct SA { __half2 qh[AD]; float v[AD]; float ep[8][132]; float es[128]; float wctx[8][264]; };
struct SG { float x[8][516]; float rs[8]; float gsm[32][9]; };
struct SQ { float h[8][260]; };
union  SU { SA a; SG g; SQ q; };

__global__ void __launch_bounds__(256,2) k_main(
        const float* __restrict__ vw,  const float* __restrict__ vb,
        const float* __restrict__ Wih, const float* __restrict__ Whh,
        const float* __restrict__ Wdec, const float* __restrict__ bdec){
    __shared__ SU sm;
    __shared__ unsigned s_chunk;
    const int c   = blockIdx.x;
    const int tid = threadIdx.x;
    const int l   = tid & 31, w = tid >> 5;
    unsigned gen = 0;
    const float vb0 = vb[0];
    float c_state = 0.f;                      // cell state (valid in G-CTAs, tid<64)

    for (int t = 0; t < TO; t++){
        // ======== Phase A : attention — dynamic chunks (b, eighth of t) ========
        const unsigned baseA = (unsigned)t * 1024u;
        for (;;){
            if (tid == 0) s_chunk = atomicAdd(&g_ticketA, 1u);
            __syncthreads();                               // publish s_chunk
            const unsigned rel = s_chunk - baseA;          // uniform snapshot
            const bool done = (rel >= 512u);
            if (!done){
                const int b  = (int)(rel >> 3), e8 = (int)(rel & 7);
                const int t0 = e8 * 128;
                const int len = g_len[b];
                if (t0 < len){
                    {   // stage q (fp16 dup) + v (f32)
                        float qf = __ldcg(&g_q[b*AD + tid]);
                        sm.a.qh[tid] = __half2half2(__float2half(qf));
                        sm.a.v[tid]  = vw[tid];
                    }
                    __syncthreads();
                    // ---- energy: warp w owns a = w+8k; lane l owns t = t0+4l..+4 ----
                    float e4[4] = {0.f,0.f,0.f,0.f};
                    {
                        const uint2* ap = (const uint2*)g_attn_t
                                        + ((((size_t)(b*AD + w))*TE + t0) >> 2) + l;
                        const size_t astep = (size_t)8*(TE>>2);
                        #pragma unroll 8
                        for (int k = 0; k < 32; k++){
                            const int a = w + 8*k;
                            uint2 x = __ldcg(ap); ap += astep;
                            __half2 qa = sm.a.qh[a];
                            float  va = sm.a.v[a];
                            __half2 h0 = __hadd2(*(__half2*)&x.x, qa);
                            __half2 h1 = __hadd2(*(__half2*)&x.y, qa);
                            unsigned r0, r1;
                            asm("tanh.approx.f16x2 %0, %1;" : "=r"(r0) : "r"(*(unsigned*)&h0));
                            asm("tanh.approx.f16x2 %0, %1;" : "=r"(r1) : "r"(*(unsigned*)&h1));
                            float2 f0 = __half22float2(*(__half2*)&r0);
                            float2 f1 = __half22float2(*(__half2*)&r1);
                            e4[0] = fmaf(va, f0.x, e4[0]); e4[1] = fmaf(va, f0.y, e4[1]);
                            e4[2] = fmaf(va, f1.x, e4[2]); e4[3] = fmaf(va, f1.y, e4[3]);
                        }
                    }
                    #pragma unroll
                    for (int i=0;i<4;i++) sm.a.ep[w][l*4+i] = e4[i];
                    __syncthreads();
                    // ---- combine warps, exp, mask ----
                    if (tid < 128){
                        float s = 0.f;
                        #pragma unroll
                        for (int ww=0;ww<8;ww++) s += sm.a.ep[ww][tid];
                        sm.a.es[tid] = (t0 + tid < len) ? __expf(s + vb0) : 0.f;
                    }
                    __syncthreads();
                    if (tid < 32){
                        float s = sm.a.es[tid] + sm.a.es[tid+32] + sm.a.es[tid+64] + sm.a.es[tid+96];
                        #pragma unroll
                        for (int off=16; off; off>>=1) s += __shfl_xor_sync(0xffffffffu, s, off);
                        if (tid == 0) __stcg(&g_sump[b*8 + e8], s);
                    }
                    // ---- context: warp w owns t-sub [t0+w*16,+16), lane l owns d = 8l..+8 ----
                    // FIXED trip count (16): es[] is exactly 0 for t >= len, and g_enc_h is
                    // fully populated for all t, so masked iterations add 0.0f exactly.
                    float ca[8];
                    #pragma unroll
                    for (int i=0;i<8;i++) ca[i] = 0.f;
                    {
                        const int baset = t0 + w*16;
                        const uint4* ep4 = (const uint4*)g_enc_h + (((size_t)(b*TE + baset)) << 5) + l;
                        #pragma unroll
                        for (int i=0;i<16;i++){
                            float ev = sm.a.es[w*16 + i];
                            uint4 x = __ldcg(ep4 + i*32);
                            float2 f0 = __half22float2(*(__half2*)&x.x);
                            float2 f1 = __half22float2(*(__half2*)&x.y);
                            float2 f2 = __half22float2(*(__half2*)&x.z);
                            float2 f3 = __half22float2(*(__half2*)&x.w);
                            ca[0] = fmaf(ev, f0.x, ca[0]); ca[1] = fmaf(ev, f0.y, ca[1]);
                            ca[2] = fmaf(ev, f1.x, ca[2]); ca[3] = fmaf(ev, f1.y, ca[3]);
                            ca[4] = fmaf(ev, f2.x, ca[4]); ca[5] = fmaf(ev, f2.y, ca[5]);
                            ca[6] = fmaf(ev, f3.x, ca[6]); ca[7] = fmaf(ev, f3.y, ca[7]);
                        }
                    }
                    #pragma unroll
                    for (int j=0;j<8;j++) sm.a.wctx[w][l*8+j] = ca[j];
                    __syncthreads();
                    {
                        float s = 0.f;
                        #pragma unroll
                        for (int ww=0;ww<8;ww++) s += sm.a.wctx[ww][tid];
                        __stcg(&g_ctxp[(size_t)(b*8 + e8)*ED + tid], s);
                    }
                }
            }
            __syncthreads();                 // protect s_chunk + smem reuse on ALL paths
            if (done) break;
        }
        gsync(gen);
        if (c == 0 && tid == 0) atomicMax(&g_ticketA, (unsigned)(t+1) * 1024u);

        // ======== Phase G : gates + cell update (CTAs 0..255 : jblock x bblock) ========
        if (c < 256){
            const int jb = c >> 3;              // 32 j-blocks of 8
            const int b0 = (c & 7) * 8;         // 8 b-blocks of 8
            if (tid < 8){
                int b = b0 + tid;
                float ssum = 0.f;
                #pragma unroll
                for (int e=0;e<8;e++) ssum += __ldcg(&g_sump[b*8 + e]);
                sm.g.rs[tid] = __fdividef(1.f, ssum);
            }
            __syncthreads();
            const int ph = t & 1;
            for (int idx = tid; idx < 8*512; idx += 256){
                int bb = idx >> 9, k = idx & 511;
                int b = b0 + bb;
                float v;
                if (k < 256){
                    float s = 0.f;
                    #pragma unroll
                    for (int e=0;e<8;e++) s += __ldcg(&g_ctxp[(size_t)(b*8+e)*ED + k]);
                    v = s * sm.g.rs[bb];
                } else {
                    v = __ldcg(&g_h[ph][b*HD + (k - 256)]);
                }
                sm.g.x[bb][k] = v;
            }
            __syncthreads();
            // ctx history store (only j-block 0 CTAs own it)
            if (jb == 0){
                for (int idx = tid; idx < 8*256; idx += 256){
                    int bb = idx >> 8, k = idx & 255;
                    __stcg(&g_chist[(size_t)t*(BB*ED) + (b0+bb)*ED + k], sm.g.x[bb][k]);
                }
            }
            // GEMM: thread = (row rr = 4gates x 8j, bb)
            const int rr = tid >> 3, bb = tid & 7;
            const int r = (rr >> 3)*256 + jb*8 + (rr & 7);
            const int b = b0 + bb;
            float a0 = __ldcg(&g_gpre[((size_t)t*1024 + r)*64 + b]);
            float a1 = 0.f, a2 = 0.f, a3 = 0.f;
            const float4* w1 = (const float4*)Wih + (size_t)r*128 + 64;   // ctx cols
            const float4* w2 = (const float4*)Whh + (size_t)r*64;
            const float4* x1 = (const float4*)sm.g.x[bb];
            const float4* x2 = x1 + 64;
            #pragma unroll 4
            for (int k=0;k<64;k++){
                float4 ww = w1[k], xx = x1[k];
                a0 = fmaf(ww.x,xx.x,a0); a1 = fmaf(ww.y,xx.y,a1);
                a2 = fmaf(ww.z,xx.z,a2); a3 = fmaf(ww.w,xx.w,a3);
            }
            #pragma unroll 4
            for (int k=0;k<64;k++){
                float4 ww = w2[k], xx = x2[k];
                a0 = fmaf(ww.x,xx.x,a0); a1 = fmaf(ww.y,xx.y,a1);
                a2 = fmaf(ww.z,xx.z,a2); a3 = fmaf(ww.w,xx.w,a3);
            }
            sm.g.gsm[rr][bb] = (a0+a1) + (a2+a3);
            __syncthreads();
            if (tid < 64){
                const int jj = tid >> 3, bb2 = tid & 7;
                float gi = sm.g.gsm[ 0 + jj][bb2];
                float gf = sm.g.gsm[ 8 + jj][bb2];
                float gg = sm.g.gsm[16 + jj][bb2];
                float go = sm.g.gsm[24 + jj][bb2];
                float cn = sigm(gf)*c_state + sigm(gi)*tanh_acc(gg);
                float hn = sigm(go)*tanh_acc(cn);
                c_state = cn;
                const int b2 = b0 + bb2, j = jb*8 + jj;
                __stcg(&g_h[(t+1)&1][b2*HD + j], hn);
                __stcg(&g_hhist[(size_t)t*(BB*HD) + b2*HD + j], hn);
            }
        }
        gsync(gen);

        // ======== Phase Q : next query q = Wdec @ h_new + bdec (CTAs 0..255) ========
        if (c < 256){
            const int ra = c >> 3, b0 = (c & 7) * 8;
            const int ph1 = (t+1) & 1;
            for (int idx = tid; idx < 8*256; idx += 256)
                sm.q.h[idx >> 8][idx & 255] = __ldcg(&g_h[ph1][(b0 + (idx >> 8))*HD + (idx & 255)]);
            __syncthreads();
            if (tid < 64){
                const int ar = tid >> 3, bb = tid & 7;
                const int a = ra*8 + ar;
                float q0 = bdec[a], q1 = 0.f, q2 = 0.f, q3 = 0.f;
                const float4* wv = (const float4*)Wdec + (size_t)a*64;
                const float4* hv = (const float4*)sm.q.h[bb];
                #pragma unroll 8
                for (int k=0;k<64;k++){
                    float4 ww = wv[k], xx = hv[k];
                    q0 = fmaf(ww.x,xx.x,q0); q1 = fmaf(ww.y,xx.y,q1);
                    q2 = fmaf(ww.z,xx.z,q2); q3 = fmaf(ww.w,xx.w,q3);
                }
                __stcg(&g_q[(b0+bb)*AD + a], (q0+q1) + (q2+q3));
            }
            __syncthreads();
        }
        gsync(gen);
    }
}

// ---------------- epilogue: mel + stop heads from history ----------------
__global__ void __launch_bounds__(256) k_heads(const float* __restrict__ melW,
                                               const float* __restrict__ melb,
                                               const float* __restrict__ stopW,
                                               const float* __restrict__ stopb,
                                               float* __restrict__ out){
    __shared__ float comb[16][520];
    const int b = blockIdx.y, t0 = blockIdx.x * 16;
    const int tid = threadIdx.x;
    for (int idx = tid; idx < 16*256; idx += 256){
        int tt = idx >> 8, k = idx & 255;
        int t = t0 + tt;
        float hv = 0.f, cv = 0.f;
        if (t < TO){
            hv = g_hhist[(size_t)t*(BB*HD) + b*HD + k];
            cv = g_chist[(size_t)t*(BB*ED) + b*ED + k];
        }
        comb[tt][k] = hv; comb[tt][256+k] = cv;
    }
    __syncthreads();
    for (int idx = tid; idx < 16*81; idx += 256){
        int tt = idx / 81, n = idx - tt*81;
        int t = t0 + tt;
        if (t >= TO) continue;
        const float4* wv = (const float4*)((n < 80) ? (melW + n*512) : stopW);
        float a0 = (n < 80) ? melb[n] : stopb[0];
        float a1 = 0.f, a2 = 0.f, a3 = 0.f;
        const float4* cv = (const float4*)comb[tt];
        #pragma unroll 4
        for (int k=0;k<128;k++){
            float4 ww = wv[k], xx = cv[k];
            a0 = fmaf(ww.x,xx.x,a0); a1 = fmaf(ww.y,xx.y,a1);
            a2 = fmaf(ww.z,xx.z,a2); a3 = fmaf(ww.w,xx.w,a3);
        }
        float r = (a0+a1) + (a2+a3);
        if (n < 80) out[(b*TO + t)*NM + n] = r;
        else        out[(size_t)BB*TO*NM + b*TO + t] = r;
    }
}

// ---------------- launch ----------------
extern "C" void kernel_launch(void* const* d_in, const int* in_sizes, int n_in,
                              void* d_out, int out_size){
    (void)in_sizes; (void)n_in; (void)out_size;
    const float* enc  = (const float*)d_in[0];
    const float* tm   = (const float*)d_in[1];
    const float* Wenc = (const float*)d_in[2];
    const float* benc = (const float*)d_in[3];
    const float* Wdec = (const float*)d_in[4];
    const float* bdec = (const float*)d_in[5];
    const float* vw   = (const float*)d_in[6];
    const float* vb   = (const float*)d_in[7];
    const float* W1   = (const float*)d_in[8];
    const float* b1   = (const float*)d_in[9];
    const float* W2   = (const float*)d_in[10];
    const float* b2   = (const float*)d_in[11];
    const float* Wih  = (const float*)d_in[12];
    const float* Whh  = (const float*)d_in[13];
    const float* bih  = (const float*)d_in[14];
    const float* bhh  = (const float*)d_in[15];
    const float* melW = (const float*)d_in[16];
    const float* melb = (const float*)d_in[17];
    const float* stopW= (const float*)d_in[18];
    const float* stopb= (const float*)d_in[19];
    const float* mask = (const float*)d_in[20];
    float* out = (float*)d_out;

    k_prep_enc<<<dim3(64,64),256>>>(enc, Wenc, benc);
    k_prenet  <<<dim3(40,64),256>>>(tm, W1, b1, W2, b2);
    k_pregate <<<dim3(8,500),256>>>(Wih, bih, bhh);
    k_init    <<<64,256>>>(bdec, mask);
    k_main    <<<NCTA,256>>>(vw, vb, Wih, Whh, Wdec, bdec);
    k_heads   <<<dim3(63,64),256>>>(melW, melb, stopW, stopb, out);
}

// round 16
// speedup vs baseline: 1.2718x; 1.0239x over previous
#include <cuda_runtime.h>
#include <cuda_fp16.h>

#define BB 64
#define TE 1024
#define TO 1000
#define AD 256
#define ED 256
#define HD 256
#define NM 80
#define NCTA 256
#define GSZ 32          // CTAs per group
#define NGRP 8          // independent groups (8 batches each)

// ---------------- static device scratch ----------------
__device__ __half g_attn_t[(size_t)BB*AD*TE];   // 32 MB : fp16 enc projection, TRANSPOSED [b][a][t]
__device__ __half g_enc_h [(size_t)BB*TE*ED];   // 32 MB : fp16 enc_outputs [b][t][d]
__device__ float  g_pre2  [(size_t)TO*BB*HD];   // prenet(all steps) [t*64+b][k]
__device__ float  g_gpre  [(size_t)TO*4*HD*BB]; // gate partial (pre+biases) [t][r][b]
__device__ float  g_q     [BB*AD];
__device__ float  g_h     [2][BB*HD];
__device__ float  g_ctxp  [512*ED];             // per (b, eighth) ctx partials
__device__ float  g_sump  [512];
__device__ float  g_hhist [(size_t)TO*BB*HD];   // h history (for deferred heads)
__device__ float  g_chist [(size_t)TO*BB*ED];   // ctx history
__device__ int    g_len   [BB];
__device__ unsigned g_gbar   [NGRP];            // per-group barrier counters
__device__ unsigned g_gticket[NGRP];            // per-group phase-A tickets

__device__ __forceinline__ float tanh_acc(float x){
    x = fminf(fmaxf(x, -15.f), 15.f);
    float e = __expf(2.f*x);
    return __fdividef(e - 1.f, e + 1.f);
}
__device__ __forceinline__ float sigm(float x){
    return __fdividef(1.f, 1.f + __expf(-x));
}

// ---------------- prologue 1: enc projection (fp16, transposed) + enc fp16 copy ----
__global__ void __launch_bounds__(256) k_prep_enc(const float* __restrict__ enc,
                                                  const float* __restrict__ Wenc,
                                                  const float* __restrict__ benc){
    __shared__ float4 enc_s[16][64];
    int tid = threadIdx.x;
    int b  = blockIdx.y;
    int t0 = blockIdx.x * 16;
    int base = (b*TE + t0)*ED;
    const float4* ev = (const float4*)(enc + base);
    for (int idx = tid; idx < 16*64; idx += 256) enc_s[idx>>6][idx&63] = ev[idx];
    for (int idx = tid; idx < 16*ED; idx += 256) g_enc_h[base+idx] = __float2half(enc[base+idx]);
    __syncthreads();
    float acc[16];
    #pragma unroll
    for (int i=0;i<16;i++) acc[i]=0.f;
    const float4* wv = (const float4*)Wenc + tid*64;
    for (int e=0;e<64;e++){
        float4 w = wv[e];
        #pragma unroll
        for (int i=0;i<16;i++){
            float4 x = enc_s[i][e];
            acc[i] += w.x*x.x + w.y*x.y + w.z*x.z + w.w*x.w;
        }
    }
    float bv = benc[tid];
    #pragma unroll
    for (int i=0;i<16;i++)
        g_attn_t[((size_t)(b*AD + tid))*TE + t0 + i] = __float2half(acc[i] + bv);
}

// ---------------- prologue 2: prenet for all steps ----------------
#define TT 25
__global__ void __launch_bounds__(256) k_prenet(const float* __restrict__ tm,
                                                const float* __restrict__ W1, const float* __restrict__ b1,
                                                const float* __restrict__ W2, const float* __restrict__ b2){
    __shared__ float prev_s[TT][80];
    __shared__ float pre1_s[TT][256];
    int tid = threadIdx.x;
    int b  = blockIdx.y;
    int t0 = blockIdx.x * TT;
    for (int idx = tid; idx < TT*80; idx += 256){
        int tt = idx/80, m = idx%80;
        int t = t0 + tt;
        prev_s[tt][m] = (t==0) ? 0.f : tm[(b*TO + (t-1))*NM + m];
    }
    __syncthreads();
    float acc[TT];
    #pragma unroll
    for (int i=0;i<TT;i++) acc[i]=0.f;
    {
        const float4* w1v = (const float4*)W1 + tid*20;
        for (int m=0;m<20;m++){
            float4 w = w1v[m];
            #pragma unroll
            for (int i=0;i<TT;i++){
                float4 x = ((const float4*)prev_s[i])[m];
                acc[i] += w.x*x.x + w.y*x.y + w.z*x.z + w.w*x.w;
            }
        }
    }
    float bv1 = b1[tid];
    #pragma unroll
    for (int i=0;i<TT;i++) pre1_s[i][tid] = fmaxf(acc[i] + bv1, 0.f);
    __syncthreads();
    #pragma unroll
    for (int i=0;i<TT;i++) acc[i]=0.f;
    {
        const float4* w2v = (const float4*)W2 + tid*64;
        for (int m=0;m<64;m++){
            float4 w = w2v[m];
            #pragma unroll
            for (int i=0;i<TT;i++){
                float4 x = ((const float4*)pre1_s[i])[m];
                acc[i] += w.x*x.x + w.y*x.y + w.z*x.z + w.w*x.w;
            }
        }
    }
    float bv2 = b2[tid];
    #pragma unroll
    for (int i=0;i<TT;i++) g_pre2[(size_t)(t0+i)*(BB*HD) + b*HD + tid] = fmaxf(acc[i] + bv2, 0.f);
}

// ------- prologue 3: gpre = Wih[:, :256] @ pre2 + biases — 128x128x32 tiled GEMM -------
__global__ void __launch_bounds__(256) k_pregate(const float* __restrict__ Wih,
                                                 const float* __restrict__ bih,
                                                 const float* __restrict__ bhh){
    __shared__ float As[32][132];     // [k][m]
    __shared__ float Bs[32][132];     // [k][r]
    int tid = threadIdx.x;
    int r0 = blockIdx.x * 128;
    int m0 = blockIdx.y * 128;
    int tx = tid & 15, ty = tid >> 4;
    float acc[8][8];
    #pragma unroll
    for (int i=0;i<8;i++)
        #pragma unroll
        for (int j=0;j<8;j++) acc[i][j]=0.f;
    for (int k0 = 0; k0 < 256; k0 += 32){
        for (int i = tid; i < 128*8; i += 256){
            int m = i >> 3, k4 = i & 7;
            float4 v = *(const float4*)&g_pre2[(size_t)(m0+m)*HD + k0 + k4*4];
            As[k4*4+0][m]=v.x; As[k4*4+1][m]=v.y; As[k4*4+2][m]=v.z; As[k4*4+3][m]=v.w;
            float4 w = *(const float4*)&Wih[(size_t)(r0+m)*512 + k0 + k4*4];
            Bs[k4*4+0][m]=w.x; Bs[k4*4+1][m]=w.y; Bs[k4*4+2][m]=w.z; Bs[k4*4+3][m]=w.w;
        }
        __syncthreads();
        #pragma unroll
        for (int k=0;k<32;k++){
            float am[8], bn[8];
            #pragma unroll
            for (int i=0;i<8;i++) am[i] = As[k][ty*8+i];
            #pragma unroll
            for (int j=0;j<8;j++) bn[j] = Bs[k][tx*8+j];
            #pragma unroll
            for (int i=0;i<8;i++)
                #pragma unroll
                for (int j=0;j<8;j++) acc[i][j] = fmaf(am[i], bn[j], acc[i][j]);
        }
        __syncthreads();
    }
    #pragma unroll
    for (int i=0;i<8;i++){
        int m = m0 + ty*8 + i, t = m >> 6, b = m & 63;
        #pragma unroll
        for (int j=0;j<8;j++){
            int r = r0 + tx*8 + j;
            g_gpre[((size_t)t*1024 + r)*64 + b] = acc[i][j] + bih[r] + bhh[r];
        }
    }
}

// ---------------- prologue 4: init state, lengths, partial-zeroing, counters ----
__global__ void k_init(const float* __restrict__ bdec, const float* __restrict__ mask){
    __shared__ float red[256];
    int b = blockIdx.x, tid = threadIdx.x;
    g_h[0][b*HD+tid] = 0.f;
    g_q[b*AD+tid]    = bdec[tid];
    for (int i = b*256 + tid; i < 512*ED; i += 64*256) g_ctxp[i] = 0.f;
    if (tid < 8) g_sump[b*8 + tid] = 0.f;
    float s = 0.f;
    for (int i=tid;i<TE;i+=256) s += mask[b*TE+i];
    red[tid]=s; __syncthreads();
    for (int off=128; off; off>>=1){ if (tid<off) red[tid]+=red[tid+off]; __syncthreads(); }
    if (tid==0) g_len[b] = (int)(red[0] + 0.5f);
    if (b==0 && tid<NGRP){ g_gbar[tid] = 0u; g_gticket[tid] = 0u; }
}

// -------- fence-free per-group barrier (release/acquire, 32 CTAs, no CCTL.IVALL) --------
__device__ __forceinline__ void gsync_grp(unsigned* p, unsigned &gen){
    __syncthreads();
    if (threadIdx.x == 0){
        gen += GSZ;
        asm volatile("red.release.gpu.add.u32 [%0], 1;" :: "l"(p) : "memory");
        unsigned v;
        do {
            asm volatile("ld.relaxed.gpu.u32 %0, [%1];" : "=r"(v) : "l"(p) : "memory");
        } while (v < gen);
        asm volatile("ld.acquire.gpu.u32 %0, [%1];" : "=r"(v) : "l"(p) : "memory");
    }
    __syncthreads();
}

// ---------------- persistent main kernel ----------------
struct SA { __half2 qh[AD]; float v[AD]; float ep[8][132]; float es[128]; float wctx[8][264]; };
struct SG { float x[8][516]; float rs[8]; float gsm[32][9]; };
struct SQ { float h[8][260]; };
union  SU { SA a; SG g; SQ q; };

__global__ void __launch_bounds__(256,2) k_main(
        const float* __restrict__ vw,  const float* __restrict__ vb,
        const float* __restrict__ Wih, const float* __restrict__ Whh,
        const float* __restrict__ Wdec, const float* __restrict__ bdec){
    __shared__ SU sm;
    __shared__ unsigned s_chunk;
    const int c   = blockIdx.x;
    const int tid = threadIdx.x;
    const int l   = tid & 31, w = tid >> 5;
    const int g   = c & 7;                    // group id: owns b in [8g, 8g+8)
    unsigned* gbar = &g_gbar[g];
    unsigned* gtic = &g_gticket[g];
    unsigned gen = 0;
    const float vb0 = vb[0];
    float c_state = 0.f;                      // cell state (tid<64 lanes of each CTA)

    for (int t = 0; t < TO; t++){
        // ==== Phase A : attention — group-local dynamic chunks (8b x 8 eighths) ====
        const unsigned baseA = (unsigned)t * 128u;
        for (;;){
            if (tid == 0) s_chunk = atomicAdd(gtic, 1u);
            __syncthreads();                               // publish s_chunk
            const unsigned rel = s_chunk - baseA;          // uniform snapshot
            const bool done = (rel >= 64u);
            if (!done){
                const int b  = (g << 3) + (int)(rel >> 3), e8 = (int)(rel & 7);
                const int t0 = e8 * 128;
                const int len = g_len[b];
                if (t0 < len){
                    {   // stage q (fp16 dup) + v (f32)
                        float qf = __ldcg(&g_q[b*AD + tid]);
                        sm.a.qh[tid] = __half2half2(__float2half(qf));
                        sm.a.v[tid]  = vw[tid];
                    }
                    __syncthreads();
                    // ---- energy: warp w owns a = w+8k; lane l owns t = t0+4l..+4 ----
                    float e4[4] = {0.f,0.f,0.f,0.f};
                    {
                        const uint2* ap = (const uint2*)g_attn_t
                                        + ((((size_t)(b*AD + w))*TE + t0) >> 2) + l;
                        const size_t astep = (size_t)8*(TE>>2);
                        #pragma unroll 8
                        for (int k = 0; k < 32; k++){
                            const int a = w + 8*k;
                            uint2 x = __ldcg(ap); ap += astep;
                            __half2 qa = sm.a.qh[a];
                            float  va = sm.a.v[a];
                            __half2 h0 = __hadd2(*(__half2*)&x.x, qa);
                            __half2 h1 = __hadd2(*(__half2*)&x.y, qa);
                            unsigned r0, r1;
                            asm("tanh.approx.f16x2 %0, %1;" : "=r"(r0) : "r"(*(unsigned*)&h0));
                            asm("tanh.approx.f16x2 %0, %1;" : "=r"(r1) : "r"(*(unsigned*)&h1));
                            float2 f0 = __half22float2(*(__half2*)&r0);
                            float2 f1 = __half22float2(*(__half2*)&r1);
                            e4[0] = fmaf(va, f0.x, e4[0]); e4[1] = fmaf(va, f0.y, e4[1]);
                            e4[2] = fmaf(va, f1.x, e4[2]); e4[3] = fmaf(va, f1.y, e4[3]);
                        }
                    }
                    #pragma unroll
                    for (int i=0;i<4;i++) sm.a.ep[w][l*4+i] = e4[i];
                    __syncthreads();
                    // ---- combine warps, exp, mask ----
                    if (tid < 128){
                        float s = 0.f;
                        #pragma unroll
                        for (int ww=0;ww<8;ww++) s += sm.a.ep[ww][tid];
                        sm.a.es[tid] = (t0 + tid < len) ? __expf(s + vb0) : 0.f;
                    }
                    __syncthreads();
                    if (tid < 32){
                        float s = sm.a.es[tid] + sm.a.es[tid+32] + sm.a.es[tid+64] + sm.a.es[tid+96];
                        #pragma unroll
                        for (int off=16; off; off>>=1) s += __shfl_xor_sync(0xffffffffu, s, off);
                        if (tid == 0) __stcg(&g_sump[b*8 + e8], s);
                    }
                    // ---- context: warp w owns t-sub [t0+w*16,+16), lane l owns d = 8l..+8 ----
                    // FIXED trip count (16): es[] is exactly 0 for t >= len.
                    float ca[8];
                    #pragma unroll
                    for (int i=0;i<8;i++) ca[i] = 0.f;
                    {
                        const int baset = t0 + w*16;
                        const uint4* ep4 = (const uint4*)g_enc_h + (((size_t)(b*TE + baset)) << 5) + l;
                        #pragma unroll
                        for (int i=0;i<16;i++){
                            float ev = sm.a.es[w*16 + i];
                            uint4 x = __ldcg(ep4 + i*32);
                            float2 f0 = __half22float2(*(__half2*)&x.x);
                            float2 f1 = __half22float2(*(__half2*)&x.y);
                            float2 f2 = __half22float2(*(__half2*)&x.z);
                            float2 f3 = __half22float2(*(__half2*)&x.w);
                            ca[0] = fmaf(ev, f0.x, ca[0]); ca[1] = fmaf(ev, f0.y, ca[1]);
                            ca[2] = fmaf(ev, f1.x, ca[2]); ca[3] = fmaf(ev, f1.y, ca[3]);
                            ca[4] = fmaf(ev, f2.x, ca[4]); ca[5] = fmaf(ev, f2.y, ca[5]);
                            ca[6] = fmaf(ev, f3.x, ca[6]); ca[7] = fmaf(ev, f3.y, ca[7]);
                        }
                    }
                    #pragma unroll
                    for (int j=0;j<8;j++) sm.a.wctx[w][l*8+j] = ca[j];
                    __syncthreads();
                    {
                        float s = 0.f;
                        #pragma unroll
                        for (int ww=0;ww<8;ww++) s += sm.a.wctx[ww][tid];
                        __stcg(&g_ctxp[(size_t)(b*8 + e8)*ED + tid], s);
                    }
                }
            }
            __syncthreads();                 // protect s_chunk + smem reuse on ALL paths
            if (done) break;
        }
        gsync_grp(gbar, gen);
        if (c < NGRP && tid == 0) atomicMax(&g_gticket[c], (unsigned)(t+1) * 128u);

        // ==== Phase G : gates + cell update (jb = c>>3, group's 8 b) ====
        {
            const int jb = c >> 3;              // 32 j-blocks of 8
            const int b0 = g * 8;
            if (tid < 8){
                int b = b0 + tid;
                float ssum = 0.f;
                #pragma unroll
                for (int e=0;e<8;e++) ssum += __ldcg(&g_sump[b*8 + e]);
                sm.g.rs[tid] = __fdividef(1.f, ssum);
            }
            __syncthreads();
            const int ph = t & 1;
            for (int idx = tid; idx < 8*512; idx += 256){
                int bb = idx >> 9, k = idx & 511;
                int b = b0 + bb;
                float v;
                if (k < 256){
                    float s = 0.f;
                    #pragma unroll
                    for (int e=0;e<8;e++) s += __ldcg(&g_ctxp[(size_t)(b*8+e)*ED + k]);
                    v = s * sm.g.rs[bb];
                } else {
                    v = __ldcg(&g_h[ph][b*HD + (k - 256)]);
                }
                sm.g.x[bb][k] = v;
            }
            __syncthreads();
            // ctx history store (only j-block 0 CTA of each group owns it)
            if (jb == 0){
                for (int idx = tid; idx < 8*256; idx += 256){
                    int bb = idx >> 8, k = idx & 255;
                    __stcg(&g_chist[(size_t)t*(BB*ED) + (b0+bb)*ED + k], sm.g.x[bb][k]);
                }
            }
            // GEMM: thread = (row rr = 4gates x 8j, bb)
            const int rr = tid >> 3, bb = tid & 7;
            const int r = (rr >> 3)*256 + jb*8 + (rr & 7);
            const int b = b0 + bb;
            float a0 = __ldcg(&g_gpre[((size_t)t*1024 + r)*64 + b]);
            float a1 = 0.f, a2 = 0.f, a3 = 0.f;
            const float4* w1 = (const float4*)Wih + (size_t)r*128 + 64;   // ctx cols
            const float4* w2 = (const float4*)Whh + (size_t)r*64;
            const float4* x1 = (const float4*)sm.g.x[bb];
            const float4* x2 = x1 + 64;
            #pragma unroll 4
            for (int k=0;k<64;k++){
                float4 ww = w1[k], xx = x1[k];
                a0 = fmaf(ww.x,xx.x,a0); a1 = fmaf(ww.y,xx.y,a1);
                a2 = fmaf(ww.z,xx.z,a2); a3 = fmaf(ww.w,xx.w,a3);
            }
            #pragma unroll 4
            for (int k=0;k<64;k++){
                float4 ww = w2[k], xx = x2[k];
                a0 = fmaf(ww.x,xx.x,a0); a1 = fmaf(ww.y,xx.y,a1);
                a2 = fmaf(ww.z,xx.z,a2); a3 = fmaf(ww.w,xx.w,a3);
            }
            sm.g.gsm[rr][bb] = (a0+a1) + (a2+a3);
            __syncthreads();
            if (tid < 64){
                const int jj = tid >> 3, bb2 = tid & 7;
                float gi = sm.g.gsm[ 0 + jj][bb2];
                float gf = sm.g.gsm[ 8 + jj][bb2];
                float gg = sm.g.gsm[16 + jj][bb2];
                float go = sm.g.gsm[24 + jj][bb2];
                float cn = sigm(gf)*c_state + sigm(gi)*tanh_acc(gg);
                float hn = sigm(go)*tanh_acc(cn);
                c_state = cn;
                const int b2 = b0 + bb2, j = jb*8 + jj;
                __stcg(&g_h[(t+1)&1][b2*HD + j], hn);
                __stcg(&g_hhist[(size_t)t*(BB*HD) + b2*HD + j], hn);
            }
        }
        gsync_grp(gbar, gen);

        // ==== Phase Q : next query q = Wdec @ h_new + bdec (ra = c>>3, group's 8 b) ====
        {
            const int ra = c >> 3, b0 = g * 8;
            const int ph1 = (t+1) & 1;
            for (int idx = tid; idx < 8*256; idx += 256)
                sm.q.h[idx >> 8][idx & 255] = __ldcg(&g_h[ph1][(b0 + (idx >> 8))*HD + (idx & 255)]);
            __syncthreads();
            if (tid < 64){
                const int ar = tid >> 3, bb = tid & 7;
                const int a = ra*8 + ar;
                float q0 = bdec[a], q1 = 0.f, q2 = 0.f, q3 = 0.f;
                const float4* wv = (const float4*)Wdec + (size_t)a*64;
                const float4* hv = (const float4*)sm.q.h[bb];
                #pragma unroll 8
                for (int k=0;k<64;k++){
                    float4 ww = wv[k], xx = hv[k];
                    q0 = fmaf(ww.x,xx.x,q0); q1 = fmaf(ww.y,xx.y,q1);
                    q2 = fmaf(ww.z,xx.z,q2); q3 = fmaf(ww.w,xx.w,q3);
                }
                __stcg(&g_q[(b0+bb)*AD + a], (q0+q1) + (q2+q3));
            }
            __syncthreads();
        }
        gsync_grp(gbar, gen);
    }
}

// ---------------- epilogue: mel + stop heads from history ----------------
__global__ void __launch_bounds__(256) k_heads(const float* __restrict__ melW,
                                               const float* __restrict__ melb,
                                               const float* __restrict__ stopW,
                                               const float* __restrict__ stopb,
                                               float* __restrict__ out){
    __shared__ float comb[16][520];
    const int b = blockIdx.y, t0 = blockIdx.x * 16;
    const int tid = threadIdx.x;
    for (int idx = tid; idx < 16*256; idx += 256){
        int tt = idx >> 8, k = idx & 255;
        int t = t0 + tt;
        float hv = 0.f, cv = 0.f;
        if (t < TO){
            hv = g_hhist[(size_t)t*(BB*HD) + b*HD + k];
            cv = g_chist[(size_t)t*(BB*ED) + b*ED + k];
        }
        comb[tt][k] = hv; comb[tt][256+k] = cv;
    }
    __syncthreads();
    for (int idx = tid; idx < 16*81; idx += 256){
        int tt = idx / 81, n = idx - tt*81;
        int t = t0 + tt;
        if (t >= TO) continue;
        const float4* wv = (const float4*)((n < 80) ? (melW + n*512) : stopW);
        float a0 = (n < 80) ? melb[n] : stopb[0];
        float a1 = 0.f, a2 = 0.f, a3 = 0.f;
        const float4* cv = (const float4*)comb[tt];
        #pragma unroll 4
        for (int k=0;k<128;k++){
            float4 ww = wv[k], xx = cv[k];
            a0 = fmaf(ww.x,xx.x,a0); a1 = fmaf(ww.y,xx.y,a1);
            a2 = fmaf(ww.z,xx.z,a2); a3 = fmaf(ww.w,xx.w,a3);
        }
        float r = (a0+a1) + (a2+a3);
        if (n < 80) out[(b*TO + t)*NM + n] = r;
        else        out[(size_t)BB*TO*NM + b*TO + t] = r;
    }
}

// ---------------- launch ----------------
extern "C" void kernel_launch(void* const* d_in, const int* in_sizes, int n_in,
                              void* d_out, int out_size){
    (void)in_sizes; (void)n_in; (void)out_size;
    const float* enc  = (const float*)d_in[0];
    const float* tm   = (const float*)d_in[1];
    const float* Wenc = (const float*)d_in[2];
    const float* benc = (const float*)d_in[3];
    const float* Wdec = (const float*)d_in[4];
    const float* bdec = (const float*)d_in[5];
    const float* vw   = (const float*)d_in[6];
    const float* vb   = (const float*)d_in[7];
    const float* W1   = (const float*)d_in[8];
    const float* b1   = (const float*)d_in[9];
    const float* W2   = (const float*)d_in[10];
    const float* b2   = (const float*)d_in[11];
    const float* Wih  = (const float*)d_in[12];
    const float* Whh  = (const float*)d_in[13];
    const float* bih  = (const float*)d_in[14];
    const float* bhh  = (const float*)d_in[15];
    const float* melW = (const float*)d_in[16];
    const float* melb = (const float*)d_in[17];
    const float* stopW= (const float*)d_in[18];
    const float* stopb= (const float*)d_in[19];
    const float* mask = (const float*)d_in[20];
    float* out = (float*)d_out;

    k_prep_enc<<<dim3(64,64),256>>>(enc, Wenc, benc);
    k_prenet  <<<dim3(40,64),256>>>(tm, W1, b1, W2, b2);
    k_pregate <<<dim3(8,500),256>>>(Wih, bih, bhh);
    k_init    <<<64,256>>>(bdec, mask);
    k_main    <<<NCTA,256>>>(vw, vb, Wih, Whh, Wdec, bdec);
    k_heads   <<<dim3(63,64),256>>>(melW, melb, stopW, stopb, out);
}